// round 15
// baseline (speedup 1.0000x reference)
#include <cuda_runtime.h>
#include <math.h>

#define TSEQ 100
#define BATCH 64
#define HGRU  128
#define G3    384   // 3*H

// ---------------- tf32 helpers ----------------
__device__ __forceinline__ unsigned f2tf32(float x) {
    unsigned u;
    asm("cvt.rna.tf32.f32 %0, %1;" : "=r"(u) : "f"(x));
    return u;
}

__device__ __forceinline__ void mma_tf32v(float* d, const unsigned* a, const unsigned* b) {
    asm volatile(
        "mma.sync.aligned.m16n8k8.row.col.f32.tf32.tf32.f32 "
        "{%0,%1,%2,%3}, {%4,%5,%6,%7}, {%8,%9}, {%0,%1,%2,%3};"
        : "+f"(d[0]), "+f"(d[1]), "+f"(d[2]), "+f"(d[3])
        : "r"(a[0]), "r"(a[1]), "r"(a[2]), "r"(a[3]),
          "r"(b[0]), "r"(b[1]));
}

// cp.async helpers
#define CPA(dst, src, sz) \
    asm volatile("cp.async.ca.shared.global [%0], [%1], 16, %2;" :: "r"(dst), "l"(src), "r"(sz))
#define CPC()  asm volatile("cp.async.commit_group;")
#define CPW0() asm volatile("cp.async.wait_group 0;")
#define CPW1() asm volatile("cp.async.wait_group 1;")

// ---------------- scratch (static __device__, no allocation) ----------------
__device__ float g_e[6400 * 128];      // embedded input, tf32-rounded
__device__ float g_gi[6400 * 768];     // gi for both directions (fp32)
__device__ float g_y[6400 * 256];      // layer output, tf32-rounded
__device__ float g_fcin[64 * 1024];    // [enc_h(512) | dec_h(512)], full fp32
__device__ float g_fcin_tf[64 * 1024]; // tf32-rounded copy for dec-l0 GEMM
__device__ float g_wt[884736];         // tf32 Wih: enc0@0, enc1@98304, dec0@294912, dec1@688128
__device__ float g_recw[2560000];      // tf32 recW

// ---------------- fused tf32 rounding of all 5 weight regions (one launch) ----------------
__global__ void cvt_all(const float4* __restrict__ s0, float4* __restrict__ d0,
                        const float4* __restrict__ s1, float4* __restrict__ d1,
                        const float4* __restrict__ s2, float4* __restrict__ d2,
                        const float4* __restrict__ s3, float4* __restrict__ d3,
                        const float4* __restrict__ s4, float4* __restrict__ d4) {
    int i = blockIdx.x * 256 + threadIdx.x;
    const float4* s; float4* d; int off;
    if      (i < 24576)  { s = s0; d = d0; off = i; }
    else if (i < 73728)  { s = s1; d = d1; off = i - 24576; }
    else if (i < 172032) { s = s2; d = d2; off = i - 73728; }
    else if (i < 221184) { s = s3; d = d3; off = i - 172032; }
    else if (i < 861184) { s = s4; d = d4; off = i - 221184; }
    else return;
    float4 v = s[off];
    v.x = __uint_as_float(f2tf32(v.x));
    v.y = __uint_as_float(f2tf32(v.y));
    v.z = __uint_as_float(f2tf32(v.z));
    v.w = __uint_as_float(f2tf32(v.w));
    d[off] = v;
}

// ---------------- elementwise tf32 rounding (fcin only) ----------------
__global__ void cvt_kernel(const float* __restrict__ src, float* __restrict__ dst, int n) {
    for (int i = blockIdx.x * 256 + threadIdx.x; i < n; i += gridDim.x * 256)
        dst[i] = __uint_as_float(f2tf32(src[i]));
}

// ---------------- embedding gather (writes tf32-rounded) ----------------
__global__ void embed_kernel(const int* __restrict__ x,
                             const float* __restrict__ emb,
                             float* __restrict__ e) {
    int row = blockIdx.x;                 // b*T + t
    int v = x[row];
    if (v > 9999) v = 9999;
    if (v < 0)    v = 0;
    e[row * 128 + threadIdx.x] = __uint_as_float(f2tf32(emb[v * 128 + threadIdx.x]));
}

// ---------------- classifier head GEMV: warp per output ----------------
__global__ void fc_kernel(const float* __restrict__ fcin,   // (64, 1024)
                          const float* __restrict__ W,      // (20, 1024)
                          const float* __restrict__ bias,   // (20)
                          float* __restrict__ out) {        // (64, 20)
    int wid  = (blockIdx.x * blockDim.x + threadIdx.x) >> 5;
    int lane = threadIdx.x & 31;
    if (wid >= 64 * 20) return;
    int m = wid / 20, n = wid % 20;
    const float4* a = (const float4*)(fcin + m * 1024);
    const float4* w = (const float4*)(W    + n * 1024);
    float s = 0.f;
#pragma unroll
    for (int i = lane; i < 256; i += 32) {
        float4 x = a[i], y = w[i];
        s += x.x * y.x + x.y * y.y + x.z * y.z + x.w * y.w;
    }
#pragma unroll
    for (int o = 16; o; o >>= 1) s += __shfl_xor_sync(0xffffffffu, s, o);
    if (lane == 0) out[m * 20 + n] = s + bias[n];
}

// ---------------- GRU recurrence: 2-D (col-group x k-slice) lanes + shfl reduce-scatter ----------------
// Warp w owns columns [32w, 32w+32). Lane = 8*g + s: handles 8 columns
// (colbase = 32w+8g .. +7) over k-slice [16s, 16s+16). Each lane loads only
// 64 B of h per step (8x less crossbar traffic than full-h broadcast).
// Cross-lane combine: 3-round shfl reduce-scatter over s (masks 1,2,4);
// lane (g,s) ends with the total for column 32w+8g+s == threadIdx.x,
// so the sgh store stays coalesced and the tail is unchanged.
__global__ void __launch_bounds__(384, 1)
gru_kernel(const float* __restrict__ gi_base, int rb, int rt,
           const float* __restrict__ Whh,   // (2, 384, 128)
           const float* __restrict__ bhh,   // (2, 384)
           float* __restrict__ y,           // (B, T, 256), written tf32-rounded
           float* __restrict__ hfin) {
    __shared__ __align__(16) float sh[128];
    __shared__ float sgh[G3];
    __shared__ float sgi[G3];

    int T    = threadIdx.x;   // 0..383; also the column this lane WRITES
    int b    = blockIdx.x;
    int dir  = blockIdx.y;
    int w    = T >> 5;
    int lane = T & 31;
    int g    = lane >> 3;     // 0..3 column group
    int s    = lane & 7;      // 0..7 k-slice
    int colbase = w * 32 + g * 8;
    int kbase   = s * 16;
    int s0 = s & 1, s1 = (s >> 1) & 1, s2 = (s >> 2) & 1;

    const float* gi = gi_base + dir * G3;
    float bh = bhh[dir * G3 + T];

    // weights: w2[i*8+kk] = W[colbase+i][kbase+2kk .. +1] packed along k
    unsigned long long w2[64];
#pragma unroll
    for (int i = 0; i < 8; i++) {
        const unsigned long long* Wr =
            (const unsigned long long*)(Whh + (size_t)(dir * G3 + colbase + i) * HGRU + kbase);
#pragma unroll
        for (int kk = 0; kk < 8; kk++) w2[i * 8 + kk] = Wr[kk];
    }

    if (T < HGRU) sh[T] = 0.f;
    __syncthreads();

    int tt_first = dir ? (TSEQ - 1) : 0;
    float gval = gi[(b * rb + tt_first * rt) * 768 + T];

    for (int t = 0; t < TSEQ; t++) {
        int tt = dir ? (TSEQ - 1 - t) : t;

        // prefetch next step's gi — consumed a full step later
        float gnext = 0.f;
        if (t + 1 < TSEQ) {
            int ttn = dir ? (TSEQ - 2 - t) : (t + 1);
            gnext = gi[(b * rb + ttn * rt) * 768 + T];
        }

        // per-lane partial dots: 8 columns x 16 k's, h streamed in two 8-float chunks
        unsigned long long acc[8];
#pragma unroll
        for (int i = 0; i < 8; i++) acc[i] = 0ULL;

        {
            ulonglong2 ha = *(const ulonglong2*)(sh + kbase);       // k 0..3 of slice
            ulonglong2 hb = *(const ulonglong2*)(sh + kbase + 4);   // k 4..7
#pragma unroll
            for (int i = 0; i < 8; i++) {
                asm("fma.rn.f32x2 %0, %1, %2, %0;" : "+l"(acc[i]) : "l"(w2[i * 8 + 0]), "l"(ha.x));
                asm("fma.rn.f32x2 %0, %1, %2, %0;" : "+l"(acc[i]) : "l"(w2[i * 8 + 1]), "l"(ha.y));
                asm("fma.rn.f32x2 %0, %1, %2, %0;" : "+l"(acc[i]) : "l"(w2[i * 8 + 2]), "l"(hb.x));
                asm("fma.rn.f32x2 %0, %1, %2, %0;" : "+l"(acc[i]) : "l"(w2[i * 8 + 3]), "l"(hb.y));
            }
        }
        {
            ulonglong2 ha = *(const ulonglong2*)(sh + kbase + 8);   // k 8..11
            ulonglong2 hb = *(const ulonglong2*)(sh + kbase + 12);  // k 12..15
#pragma unroll
            for (int i = 0; i < 8; i++) {
                asm("fma.rn.f32x2 %0, %1, %2, %0;" : "+l"(acc[i]) : "l"(w2[i * 8 + 4]), "l"(ha.x));
                asm("fma.rn.f32x2 %0, %1, %2, %0;" : "+l"(acc[i]) : "l"(w2[i * 8 + 5]), "l"(ha.y));
                asm("fma.rn.f32x2 %0, %1, %2, %0;" : "+l"(acc[i]) : "l"(w2[i * 8 + 6]), "l"(hb.x));
                asm("fma.rn.f32x2 %0, %1, %2, %0;" : "+l"(acc[i]) : "l"(w2[i * 8 + 7]), "l"(hb.y));
            }
        }

        // split lo/hi
        float t0, t1, t2, t3, t4, t5, t6, t7;
        {
            float lo, hi;
            asm("mov.b64 {%0,%1}, %2;" : "=f"(lo), "=f"(hi) : "l"(acc[0])); t0 = lo + hi;
            asm("mov.b64 {%0,%1}, %2;" : "=f"(lo), "=f"(hi) : "l"(acc[1])); t1 = lo + hi;
            asm("mov.b64 {%0,%1}, %2;" : "=f"(lo), "=f"(hi) : "l"(acc[2])); t2 = lo + hi;
            asm("mov.b64 {%0,%1}, %2;" : "=f"(lo), "=f"(hi) : "l"(acc[3])); t3 = lo + hi;
            asm("mov.b64 {%0,%1}, %2;" : "=f"(lo), "=f"(hi) : "l"(acc[4])); t4 = lo + hi;
            asm("mov.b64 {%0,%1}, %2;" : "=f"(lo), "=f"(hi) : "l"(acc[5])); t5 = lo + hi;
            asm("mov.b64 {%0,%1}, %2;" : "=f"(lo), "=f"(hi) : "l"(acc[6])); t6 = lo + hi;
            asm("mov.b64 {%0,%1}, %2;" : "=f"(lo), "=f"(hi) : "l"(acc[7])); t7 = lo + hi;
        }

        // reduce-scatter over s (3 rounds, 7 shfl): lane ends with column T's total
        float r0 = (s0 ? t1 : t0) + __shfl_xor_sync(0xffffffffu, s0 ? t0 : t1, 1);
        float r1 = (s0 ? t3 : t2) + __shfl_xor_sync(0xffffffffu, s0 ? t2 : t3, 1);
        float r2 = (s0 ? t5 : t4) + __shfl_xor_sync(0xffffffffu, s0 ? t4 : t5, 1);
        float r3 = (s0 ? t7 : t6) + __shfl_xor_sync(0xffffffffu, s0 ? t6 : t7, 1);
        float q0 = (s1 ? r1 : r0) + __shfl_xor_sync(0xffffffffu, s1 ? r0 : r1, 2);
        float q1 = (s1 ? r3 : r2) + __shfl_xor_sync(0xffffffffu, s1 ? r2 : r3, 2);
        float tot = (s2 ? q1 : q0) + __shfl_xor_sync(0xffffffffu, s2 ? q0 : q1, 4);

        sgh[T] = tot + bh;
        sgi[T] = gval;
        __syncthreads();

        if (T < HGRU) {
            float r = __fdividef(1.f, 1.f + __expf(-(sgi[T]        + sgh[T])));
            float z = __fdividef(1.f, 1.f + __expf(-(sgi[HGRU + T] + sgh[HGRU + T])));
            float nx = sgi[2 * HGRU + T] + r * sgh[2 * HGRU + T];
            float et = __expf(-2.f * nx);
            float n  = __fdividef(1.f - et, 1.f + et);   // tanh(nx)
            float hn = n + z * (sh[T] - n);
            sh[T] = hn;
            y[(b * TSEQ + tt) * 256 + dir * HGRU + T] = __uint_as_float(f2tf32(hn));
        }
        __syncthreads();

        gval = gnext;
    }
    if (T < HGRU) hfin[b * 1024 + dir * HGRU + T] = sh[T];
}

// ---------------- tf32 MMA GEMM, cp.async 3-stage + ldmatrix fragment loads ----------------
#define MMA_STAGES 3
#define MMA_BUF    (128 * 36)                       // floats per operand per stage
#define MMA_SMEM   (MMA_STAGES * MMA_BUF * 4 * 2)   // 110592 B
__global__ void __launch_bounds__(256, 2)
mma_tn(const float* __restrict__ A, int lda,
       const float* __restrict__ W,     // (N, K)
       const float* __restrict__ bias,  // (N)
       float* __restrict__ C,
       int M, int N, int K) {
    extern __shared__ float smem[];
    float* As = smem;                        // [3][128][36]
    float* Bs = smem + MMA_STAGES * MMA_BUF;

    int t    = threadIdx.x;
    int lane = t & 31;
    int warp = t >> 5;
    int m0 = blockIdx.y * 128;
    int n0 = blockIdx.x * 128;
    int wm = (warp & 3) * 32;
    int wn = (warp >> 2) * 64;
    int r  = lane >> 2;       // 0..7
    int c  = lane & 3;        // 0..3

    unsigned sbaseA = (unsigned)__cvta_generic_to_shared(As);
    unsigned sbaseB = (unsigned)__cvta_generic_to_shared(Bs);

    // lane-constant ldmatrix address parts
    int grp = lane >> 3, q = lane & 7;
    unsigned LA = (((unsigned)((grp & 1) * 8 + q)) * 36 + (unsigned)((grp >> 1) * 4)) * 4;
    unsigned LB = (((unsigned)((grp >> 1) * 8 + q)) * 36 + (unsigned)((grp & 1) * 4)) * 4;

    float acc[2][8][4];
#pragma unroll
    for (int mf = 0; mf < 2; mf++)
#pragma unroll
        for (int nf = 0; nf < 8; nf++)
#pragma unroll
            for (int i = 0; i < 4; i++) acc[mf][nf][i] = 0.f;

    int nch = K >> 5;    // K/32 chunks

    auto stage = [&](int buf, int k0) {
#pragma unroll
        for (int i = 0; i < 4; i++) {
            int idx = i * 256 + t;
            int row = idx >> 3;
            int c4  = (idx & 7) * 4;
            unsigned off = ((unsigned)(buf * 128 + row) * 36 + c4) * 4;
            CPA(sbaseA + off, &A[(size_t)(m0 + row) * lda + k0 + c4], (m0 + row < M) ? 16 : 0);
            CPA(sbaseB + off, &W[(size_t)(n0 + row) * K   + k0 + c4], (n0 + row < N) ? 16 : 0);
        }
    };

    auto compute = [&](int buf) {
        unsigned aB = sbaseA + (unsigned)buf * (MMA_BUF * 4);
        unsigned bB = sbaseB + (unsigned)buf * (MMA_BUF * 4);
#pragma unroll
        for (int ks = 0; ks < 4; ks++) {
            int kb = ks * 8;
            unsigned a[2][4];
#pragma unroll
            for (int mf = 0; mf < 2; mf++) {
                unsigned addr = aB + ((unsigned)((wm + mf * 16) * 36 + kb)) * 4 + LA;
                asm volatile(
                    "ldmatrix.sync.aligned.m8n8.x4.shared.b16 {%0,%1,%2,%3}, [%4];"
                    : "=r"(a[mf][0]), "=r"(a[mf][1]), "=r"(a[mf][2]), "=r"(a[mf][3])
                    : "r"(addr));
            }
#pragma unroll
            for (int p = 0; p < 4; p++) {
                unsigned b[4];
                unsigned addr = bB + ((unsigned)((wn + 16 * p) * 36 + kb)) * 4 + LB;
                asm volatile(
                    "ldmatrix.sync.aligned.m8n8.x4.shared.b16 {%0,%1,%2,%3}, [%4];"
                    : "=r"(b[0]), "=r"(b[1]), "=r"(b[2]), "=r"(b[3])
                    : "r"(addr));
                mma_tf32v(acc[0][2 * p],     a[0], b);
                mma_tf32v(acc[1][2 * p],     a[1], b);
                mma_tf32v(acc[0][2 * p + 1], a[0], b + 2);
                mma_tf32v(acc[1][2 * p + 1], a[1], b + 2);
            }
        }
    };

    // prologue: 2 chunks in flight
    stage(0, 0);  CPC();
    if (nch > 1) { stage(1, 32); CPC(); }

    int buf = 0;            // buf == ci % 3, maintained by rotation
    for (int ci = 0; ci < nch; ci++) {
        if (ci < nch - 1) { CPW1(); } else { CPW0(); }
        __syncthreads();
        if (ci + 2 < nch) {
            int nb = buf + 2; if (nb >= 3) nb -= 3;
            stage(nb, (ci + 2) * 32); CPC();
        }
        compute(buf);
        if (++buf == 3) buf = 0;
    }

    // epilogue
#pragma unroll
    for (int mf = 0; mf < 2; mf++) {
#pragma unroll
        for (int nf = 0; nf < 8; nf++) {
            int n = n0 + wn + nf * 8 + 2 * c;
            if (n >= N) continue;
            float bv0 = bias[n];
            float bv1 = bias[n + 1];
            int m = m0 + wm + mf * 16 + r;
            if (m < M) {
                *(float2*)&C[(size_t)m * N + n] =
                    make_float2(acc[mf][nf][0] + bv0, acc[mf][nf][1] + bv1);
            }
            if (m + 8 < M) {
                *(float2*)&C[(size_t)(m + 8) * N + n] =
                    make_float2(acc[mf][nf][2] + bv0, acc[mf][nf][3] + bv1);
            }
        }
    }
}

// ---------------- driver ----------------
extern "C" void kernel_launch(void* const* d_in, const int* in_sizes, int n_in,
                              void* d_out, int out_size) {
    const int* x         = (const int*)d_in[0];
    const float* emb     = (const float*)d_in[1];
    const float* eWih0   = (const float*)d_in[2];
    const float* eWhh0   = (const float*)d_in[3];
    const float* ebih0   = (const float*)d_in[4];
    const float* ebhh0   = (const float*)d_in[5];
    const float* eWih1   = (const float*)d_in[6];
    const float* eWhh1   = (const float*)d_in[7];
    const float* ebih1   = (const float*)d_in[8];
    const float* ebhh1   = (const float*)d_in[9];
    const float* dWih0   = (const float*)d_in[10];
    const float* dWhh0   = (const float*)d_in[11];
    const float* dbih0   = (const float*)d_in[12];
    const float* dbhh0   = (const float*)d_in[13];
    const float* dWih1   = (const float*)d_in[14];
    const float* dWhh1   = (const float*)d_in[15];
    const float* dbih1   = (const float*)d_in[16];
    const float* dbhh1   = (const float*)d_in[17];
    const float* fcW     = (const float*)d_in[18];
    const float* fcb     = (const float*)d_in[19];
    const float* recW    = (const float*)d_in[20];
    const float* recb    = (const float*)d_in[21];

    float* out = (float*)d_out;          // (64, 20)
    float* rec = out + 64 * 20;          // (64, 100, 10000)

    float *e, *gi, *y, *fcin, *fcin_tf, *wt, *recw;
    cudaGetSymbolAddress((void**)&e,       g_e);
    cudaGetSymbolAddress((void**)&gi,      g_gi);
    cudaGetSymbolAddress((void**)&y,       g_y);
    cudaGetSymbolAddress((void**)&fcin,    g_fcin);
    cudaGetSymbolAddress((void**)&fcin_tf, g_fcin_tf);
    cudaGetSymbolAddress((void**)&wt,      g_wt);
    cudaGetSymbolAddress((void**)&recw,    g_recw);

    cudaFuncSetAttribute(mma_tn, cudaFuncAttributeMaxDynamicSharedMemorySize, MMA_SMEM);

    dim3 gruGrid(BATCH, 2);

    // 0. pre-round all GEMM weights to tf32, one launch
    cvt_all<<<3364, 256>>>((const float4*)eWih0, (float4*)(wt + 0),
                           (const float4*)eWih1, (float4*)(wt + 98304),
                           (const float4*)dWih0, (float4*)(wt + 294912),
                           (const float4*)dWih1, (float4*)(wt + 688128),
                           (const float4*)recW,  (float4*)recw);

    // 1. embedding (tf32-rounded output)
    embed_kernel<<<6400, 128>>>(x, emb, e);

    // 2. encoder layer 0
    mma_tn<<<dim3(6, 50), 256, MMA_SMEM>>>(e, 128, wt + 0, ebih0, gi, 6400, 768, 128);
    gru_kernel<<<gruGrid, 384>>>(gi, TSEQ, 1, eWhh0, ebhh0, y, fcin + 0);

    // 3. encoder layer 1
    mma_tn<<<dim3(6, 50), 256, MMA_SMEM>>>(y, 256, wt + 98304, ebih1, gi, 6400, 768, 256);
    gru_kernel<<<gruGrid, 384>>>(gi, TSEQ, 1, eWhh1, ebhh1, y, fcin + 256);

    // 4. decoder layer 0 (constant input over T)
    cvt_kernel<<<64, 256>>>(fcin, fcin_tf, 65536);
    mma_tn<<<dim3(6, 1), 256, MMA_SMEM>>>(fcin_tf, 1024, wt + 294912, dbih0, gi, 64, 768, 512);
    gru_kernel<<<gruGrid, 384>>>(gi, 1, 0, dWhh0, dbhh0, y, fcin + 512);

    // 5. decoder layer 1 (output y = rec_seq)
    mma_tn<<<dim3(6, 50), 256, MMA_SMEM>>>(y, 256, wt + 688128, dbih1, gi, 6400, 768, 256);
    gru_kernel<<<gruGrid, 384>>>(gi, TSEQ, 1, dWhh1, dbhh1, y, fcin + 768);

    // 6. classifier head (fp32 GEMV, warp per output)
    fc_kernel<<<160, 256>>>(fcin, fcW, fcb, out);

    // 7. reconstruction: rec = rec_seq @ rec_W^T + rec_b
    mma_tn<<<dim3(79, 50), 256, MMA_SMEM>>>(y, 256, recw, recb, rec, 6400, 10000, 256);
}

// round 16
// speedup vs baseline: 1.0194x; 1.0194x over previous
#include <cuda_runtime.h>
#include <math.h>

#define TSEQ 100
#define BATCH 64
#define HGRU  128
#define G3    384   // 3*H

// ---------------- tf32 helpers ----------------
__device__ __forceinline__ unsigned f2tf32(float x) {
    unsigned u;
    asm("cvt.rna.tf32.f32 %0, %1;" : "=r"(u) : "f"(x));
    return u;
}

__device__ __forceinline__ void mma_tf32v(float* d, const unsigned* a, const unsigned* b) {
    asm volatile(
        "mma.sync.aligned.m16n8k8.row.col.f32.tf32.tf32.f32 "
        "{%0,%1,%2,%3}, {%4,%5,%6,%7}, {%8,%9}, {%0,%1,%2,%3};"
        : "+f"(d[0]), "+f"(d[1]), "+f"(d[2]), "+f"(d[3])
        : "r"(a[0]), "r"(a[1]), "r"(a[2]), "r"(a[3]),
          "r"(b[0]), "r"(b[1]));
}

// cp.async helpers
#define CPA(dst, src, sz) \
    asm volatile("cp.async.ca.shared.global [%0], [%1], 16, %2;" :: "r"(dst), "l"(src), "r"(sz))
#define CPC()  asm volatile("cp.async.commit_group;")
#define CPW0() asm volatile("cp.async.wait_group 0;")
#define CPW1() asm volatile("cp.async.wait_group 1;")

// ---------------- scratch (static __device__, no allocation) ----------------
__device__ float g_e[6400 * 128];      // embedded input, tf32-rounded
__device__ float g_gi[6400 * 768];     // gi for both directions (fp32)
__device__ float g_y[6400 * 256];      // layer output, tf32-rounded
__device__ float g_fcin[64 * 1024];    // [enc_h(512) | dec_h(512)], full fp32
__device__ float g_wt[884736];         // tf32 Wih: enc0@0, enc1@98304, dec0@294912, dec1@688128

// ---------------- fused tf32 rounding of the 4 Wih regions (one launch) ----------------
// float4 units: 24576 | 49152 | 98304 | 49152; prefix 24576,73728,172032,221184
__global__ void cvt4(const float4* __restrict__ s0, float4* __restrict__ d0,
                     const float4* __restrict__ s1, float4* __restrict__ d1,
                     const float4* __restrict__ s2, float4* __restrict__ d2,
                     const float4* __restrict__ s3, float4* __restrict__ d3) {
    int i = blockIdx.x * 256 + threadIdx.x;
    const float4* s; float4* d; int off;
    if      (i < 24576)  { s = s0; d = d0; off = i; }
    else if (i < 73728)  { s = s1; d = d1; off = i - 24576; }
    else if (i < 172032) { s = s2; d = d2; off = i - 73728; }
    else if (i < 221184) { s = s3; d = d3; off = i - 172032; }
    else return;
    float4 v = s[off];
    v.x = __uint_as_float(f2tf32(v.x));
    v.y = __uint_as_float(f2tf32(v.y));
    v.z = __uint_as_float(f2tf32(v.z));
    v.w = __uint_as_float(f2tf32(v.w));
    d[off] = v;
}

// ---------------- embedding gather (float4, writes tf32-rounded) ----------------
__global__ void embed_kernel(const int* __restrict__ x,
                             const float* __restrict__ emb,
                             float* __restrict__ e) {
    int idx = blockIdx.x * 256 + threadIdx.x;   // 204800 float4 total
    if (idx >= 6400 * 32) return;
    int row = idx >> 5;
    int c4  = idx & 31;
    int v = x[row];
    if (v > 9999) v = 9999;
    if (v < 0)    v = 0;
    float4 t = ((const float4*)emb)[v * 32 + c4];
    t.x = __uint_as_float(f2tf32(t.x));
    t.y = __uint_as_float(f2tf32(t.y));
    t.z = __uint_as_float(f2tf32(t.z));
    t.w = __uint_as_float(f2tf32(t.w));
    ((float4*)e)[row * 32 + c4] = t;
}

// ---------------- classifier head GEMV: warp per output ----------------
__global__ void fc_kernel(const float* __restrict__ fcin,   // (64, 1024)
                          const float* __restrict__ W,      // (20, 1024)
                          const float* __restrict__ bias,   // (20)
                          float* __restrict__ out) {        // (64, 20)
    int wid  = (blockIdx.x * blockDim.x + threadIdx.x) >> 5;
    int lane = threadIdx.x & 31;
    if (wid >= 64 * 20) return;
    int m = wid / 20, n = wid % 20;
    const float4* a = (const float4*)(fcin + m * 1024);
    const float4* w = (const float4*)(W    + n * 1024);
    float s = 0.f;
#pragma unroll
    for (int i = lane; i < 256; i += 32) {
        float4 x = a[i], y = w[i];
        s += x.x * y.x + x.y * y.y + x.z * y.z + x.w * y.w;
    }
#pragma unroll
    for (int o = 16; o; o >>= 1) s += __shfl_xor_sync(0xffffffffu, s, o);
    if (lane == 0) out[m * 20 + n] = s + bias[n];
}

// ---------------- GRU recurrence: 2-D (col-group x k-slice) lanes + shfl reduce-scatter ----------------
// (r15 version, frozen: near its latency floor given RF-resident weights)
__global__ void __launch_bounds__(384, 1)
gru_kernel(const float* __restrict__ gi_base, int rb, int rt,
           const float* __restrict__ Whh,   // (2, 384, 128)
           const float* __restrict__ bhh,   // (2, 384)
           float* __restrict__ y,           // (B, T, 256), written tf32-rounded
           float* __restrict__ hfin) {
    __shared__ __align__(16) float sh[128];
    __shared__ float sgh[G3];
    __shared__ float sgi[G3];

    int T    = threadIdx.x;   // 0..383; also the column this lane WRITES
    int b    = blockIdx.x;
    int dir  = blockIdx.y;
    int w    = T >> 5;
    int lane = T & 31;
    int g    = lane >> 3;     // 0..3 column group
    int s    = lane & 7;      // 0..7 k-slice
    int colbase = w * 32 + g * 8;
    int kbase   = s * 16;
    int s0 = s & 1, s1 = (s >> 1) & 1, s2 = (s >> 2) & 1;

    const float* gi = gi_base + dir * G3;
    float bh = bhh[dir * G3 + T];

    // weights: w2[i*8+kk] = W[colbase+i][kbase+2kk .. +1] packed along k
    unsigned long long w2[64];
#pragma unroll
    for (int i = 0; i < 8; i++) {
        const unsigned long long* Wr =
            (const unsigned long long*)(Whh + (size_t)(dir * G3 + colbase + i) * HGRU + kbase);
#pragma unroll
        for (int kk = 0; kk < 8; kk++) w2[i * 8 + kk] = Wr[kk];
    }

    if (T < HGRU) sh[T] = 0.f;
    __syncthreads();

    int tt_first = dir ? (TSEQ - 1) : 0;
    float gval = gi[(b * rb + tt_first * rt) * 768 + T];

    for (int t = 0; t < TSEQ; t++) {
        int tt = dir ? (TSEQ - 1 - t) : t;

        // prefetch next step's gi — consumed a full step later
        float gnext = 0.f;
        if (t + 1 < TSEQ) {
            int ttn = dir ? (TSEQ - 2 - t) : (t + 1);
            gnext = gi[(b * rb + ttn * rt) * 768 + T];
        }

        // per-lane partial dots: 8 columns x 16 k's, h streamed in two 8-float chunks
        unsigned long long acc[8];
#pragma unroll
        for (int i = 0; i < 8; i++) acc[i] = 0ULL;

        {
            ulonglong2 ha = *(const ulonglong2*)(sh + kbase);       // k 0..3 of slice
            ulonglong2 hb = *(const ulonglong2*)(sh + kbase + 4);   // k 4..7
#pragma unroll
            for (int i = 0; i < 8; i++) {
                asm("fma.rn.f32x2 %0, %1, %2, %0;" : "+l"(acc[i]) : "l"(w2[i * 8 + 0]), "l"(ha.x));
                asm("fma.rn.f32x2 %0, %1, %2, %0;" : "+l"(acc[i]) : "l"(w2[i * 8 + 1]), "l"(ha.y));
                asm("fma.rn.f32x2 %0, %1, %2, %0;" : "+l"(acc[i]) : "l"(w2[i * 8 + 2]), "l"(hb.x));
                asm("fma.rn.f32x2 %0, %1, %2, %0;" : "+l"(acc[i]) : "l"(w2[i * 8 + 3]), "l"(hb.y));
            }
        }
        {
            ulonglong2 ha = *(const ulonglong2*)(sh + kbase + 8);   // k 8..11
            ulonglong2 hb = *(const ulonglong2*)(sh + kbase + 12);  // k 12..15
#pragma unroll
            for (int i = 0; i < 8; i++) {
                asm("fma.rn.f32x2 %0, %1, %2, %0;" : "+l"(acc[i]) : "l"(w2[i * 8 + 4]), "l"(ha.x));
                asm("fma.rn.f32x2 %0, %1, %2, %0;" : "+l"(acc[i]) : "l"(w2[i * 8 + 5]), "l"(ha.y));
                asm("fma.rn.f32x2 %0, %1, %2, %0;" : "+l"(acc[i]) : "l"(w2[i * 8 + 6]), "l"(hb.x));
                asm("fma.rn.f32x2 %0, %1, %2, %0;" : "+l"(acc[i]) : "l"(w2[i * 8 + 7]), "l"(hb.y));
            }
        }

        // split lo/hi
        float t0, t1, t2, t3, t4, t5, t6, t7;
        {
            float lo, hi;
            asm("mov.b64 {%0,%1}, %2;" : "=f"(lo), "=f"(hi) : "l"(acc[0])); t0 = lo + hi;
            asm("mov.b64 {%0,%1}, %2;" : "=f"(lo), "=f"(hi) : "l"(acc[1])); t1 = lo + hi;
            asm("mov.b64 {%0,%1}, %2;" : "=f"(lo), "=f"(hi) : "l"(acc[2])); t2 = lo + hi;
            asm("mov.b64 {%0,%1}, %2;" : "=f"(lo), "=f"(hi) : "l"(acc[3])); t3 = lo + hi;
            asm("mov.b64 {%0,%1}, %2;" : "=f"(lo), "=f"(hi) : "l"(acc[4])); t4 = lo + hi;
            asm("mov.b64 {%0,%1}, %2;" : "=f"(lo), "=f"(hi) : "l"(acc[5])); t5 = lo + hi;
            asm("mov.b64 {%0,%1}, %2;" : "=f"(lo), "=f"(hi) : "l"(acc[6])); t6 = lo + hi;
            asm("mov.b64 {%0,%1}, %2;" : "=f"(lo), "=f"(hi) : "l"(acc[7])); t7 = lo + hi;
        }

        // reduce-scatter over s (3 rounds, 7 shfl): lane ends with column T's total
        float r0 = (s0 ? t1 : t0) + __shfl_xor_sync(0xffffffffu, s0 ? t0 : t1, 1);
        float r1 = (s0 ? t3 : t2) + __shfl_xor_sync(0xffffffffu, s0 ? t2 : t3, 1);
        float r2 = (s0 ? t5 : t4) + __shfl_xor_sync(0xffffffffu, s0 ? t4 : t5, 1);
        float r3 = (s0 ? t7 : t6) + __shfl_xor_sync(0xffffffffu, s0 ? t6 : t7, 1);
        float q0 = (s1 ? r1 : r0) + __shfl_xor_sync(0xffffffffu, s1 ? r0 : r1, 2);
        float q1 = (s1 ? r3 : r2) + __shfl_xor_sync(0xffffffffu, s1 ? r2 : r3, 2);
        float tot = (s2 ? q1 : q0) + __shfl_xor_sync(0xffffffffu, s2 ? q0 : q1, 4);

        sgh[T] = tot + bh;
        sgi[T] = gval;
        __syncthreads();

        if (T < HGRU) {
            float r = __fdividef(1.f, 1.f + __expf(-(sgi[T]        + sgh[T])));
            float z = __fdividef(1.f, 1.f + __expf(-(sgi[HGRU + T] + sgh[HGRU + T])));
            float nx = sgi[2 * HGRU + T] + r * sgh[2 * HGRU + T];
            float et = __expf(-2.f * nx);
            float n  = __fdividef(1.f - et, 1.f + et);   // tanh(nx)
            float hn = n + z * (sh[T] - n);
            sh[T] = hn;
            y[(b * TSEQ + tt) * 256 + dir * HGRU + T] = __uint_as_float(f2tf32(hn));
        }
        __syncthreads();

        gval = gnext;
    }
    if (T < HGRU) hfin[b * 1024 + dir * HGRU + T] = sh[T];
}

// ---------------- tf32 MMA GEMM, cp.async 3-stage + ldmatrix fragment loads ----------------
// Inputs may be raw fp32: HMMA-tf32 truncates the low mantissa bits (RZ).
#define MMA_STAGES 3
#define MMA_BUF    (128 * 36)                       // floats per operand per stage
#define MMA_SMEM   (MMA_STAGES * MMA_BUF * 4 * 2)   // 110592 B
__global__ void __launch_bounds__(256, 2)
mma_tn(const float* __restrict__ A, int lda,
       const float* __restrict__ W,     // (N, K)
       const float* __restrict__ bias,  // (N)
       float* __restrict__ C,
       int M, int N, int K) {
    extern __shared__ float smem[];
    float* As = smem;                        // [3][128][36]
    float* Bs = smem + MMA_STAGES * MMA_BUF;

    int t    = threadIdx.x;
    int lane = t & 31;
    int warp = t >> 5;
    int m0 = blockIdx.y * 128;
    int n0 = blockIdx.x * 128;
    int wm = (warp & 3) * 32;
    int wn = (warp >> 2) * 64;
    int r  = lane >> 2;       // 0..7
    int c  = lane & 3;        // 0..3

    unsigned sbaseA = (unsigned)__cvta_generic_to_shared(As);
    unsigned sbaseB = (unsigned)__cvta_generic_to_shared(Bs);

    // lane-constant ldmatrix address parts
    int grp = lane >> 3, q = lane & 7;
    unsigned LA = (((unsigned)((grp & 1) * 8 + q)) * 36 + (unsigned)((grp >> 1) * 4)) * 4;
    unsigned LB = (((unsigned)((grp >> 1) * 8 + q)) * 36 + (unsigned)((grp & 1) * 4)) * 4;

    float acc[2][8][4];
#pragma unroll
    for (int mf = 0; mf < 2; mf++)
#pragma unroll
        for (int nf = 0; nf < 8; nf++)
#pragma unroll
            for (int i = 0; i < 4; i++) acc[mf][nf][i] = 0.f;

    int nch = K >> 5;    // K/32 chunks

    auto stage = [&](int buf, int k0) {
#pragma unroll
        for (int i = 0; i < 4; i++) {
            int idx = i * 256 + t;
            int row = idx >> 3;
            int c4  = (idx & 7) * 4;
            unsigned off = ((unsigned)(buf * 128 + row) * 36 + c4) * 4;
            CPA(sbaseA + off, &A[(size_t)(m0 + row) * lda + k0 + c4], (m0 + row < M) ? 16 : 0);
            CPA(sbaseB + off, &W[(size_t)(n0 + row) * K   + k0 + c4], (n0 + row < N) ? 16 : 0);
        }
    };

    auto compute = [&](int buf) {
        unsigned aB = sbaseA + (unsigned)buf * (MMA_BUF * 4);
        unsigned bB = sbaseB + (unsigned)buf * (MMA_BUF * 4);
#pragma unroll
        for (int ks = 0; ks < 4; ks++) {
            int kb = ks * 8;
            unsigned a[2][4];
#pragma unroll
            for (int mf = 0; mf < 2; mf++) {
                unsigned addr = aB + ((unsigned)((wm + mf * 16) * 36 + kb)) * 4 + LA;
                asm volatile(
                    "ldmatrix.sync.aligned.m8n8.x4.shared.b16 {%0,%1,%2,%3}, [%4];"
                    : "=r"(a[mf][0]), "=r"(a[mf][1]), "=r"(a[mf][2]), "=r"(a[mf][3])
                    : "r"(addr));
            }
#pragma unroll
            for (int p = 0; p < 4; p++) {
                unsigned b[4];
                unsigned addr = bB + ((unsigned)((wn + 16 * p) * 36 + kb)) * 4 + LB;
                asm volatile(
                    "ldmatrix.sync.aligned.m8n8.x4.shared.b16 {%0,%1,%2,%3}, [%4];"
                    : "=r"(b[0]), "=r"(b[1]), "=r"(b[2]), "=r"(b[3])
                    : "r"(addr));
                mma_tf32v(acc[0][2 * p],     a[0], b);
                mma_tf32v(acc[1][2 * p],     a[1], b);
                mma_tf32v(acc[0][2 * p + 1], a[0], b + 2);
                mma_tf32v(acc[1][2 * p + 1], a[1], b + 2);
            }
        }
    };

    // prologue: 2 chunks in flight
    stage(0, 0);  CPC();
    if (nch > 1) { stage(1, 32); CPC(); }

    int buf = 0;            // buf == ci % 3, maintained by rotation
    for (int ci = 0; ci < nch; ci++) {
        if (ci < nch - 1) { CPW1(); } else { CPW0(); }
        __syncthreads();
        if (ci + 2 < nch) {
            int nb = buf + 2; if (nb >= 3) nb -= 3;
            stage(nb, (ci + 2) * 32); CPC();
        }
        compute(buf);
        if (++buf == 3) buf = 0;
    }

    // epilogue
#pragma unroll
    for (int mf = 0; mf < 2; mf++) {
#pragma unroll
        for (int nf = 0; nf < 8; nf++) {
            int n = n0 + wn + nf * 8 + 2 * c;
            if (n >= N) continue;
            float bv0 = bias[n];
            float bv1 = bias[n + 1];
            int m = m0 + wm + mf * 16 + r;
            if (m < M) {
                *(float2*)&C[(size_t)m * N + n] =
                    make_float2(acc[mf][nf][0] + bv0, acc[mf][nf][1] + bv1);
            }
            if (m + 8 < M) {
                *(float2*)&C[(size_t)(m + 8) * N + n] =
                    make_float2(acc[mf][nf][2] + bv0, acc[mf][nf][3] + bv1);
            }
        }
    }
}

// ---------------- driver ----------------
extern "C" void kernel_launch(void* const* d_in, const int* in_sizes, int n_in,
                              void* d_out, int out_size) {
    const int* x         = (const int*)d_in[0];
    const float* emb     = (const float*)d_in[1];
    const float* eWih0   = (const float*)d_in[2];
    const float* eWhh0   = (const float*)d_in[3];
    const float* ebih0   = (const float*)d_in[4];
    const float* ebhh0   = (const float*)d_in[5];
    const float* eWih1   = (const float*)d_in[6];
    const float* eWhh1   = (const float*)d_in[7];
    const float* ebih1   = (const float*)d_in[8];
    const float* ebhh1   = (const float*)d_in[9];
    const float* dWih0   = (const float*)d_in[10];
    const float* dWhh0   = (const float*)d_in[11];
    const float* dbih0   = (const float*)d_in[12];
    const float* dbhh0   = (const float*)d_in[13];
    const float* dWih1   = (const float*)d_in[14];
    const float* dWhh1   = (const float*)d_in[15];
    const float* dbih1   = (const float*)d_in[16];
    const float* dbhh1   = (const float*)d_in[17];
    const float* fcW     = (const float*)d_in[18];
    const float* fcb     = (const float*)d_in[19];
    const float* recW    = (const float*)d_in[20];
    const float* recb    = (const float*)d_in[21];

    float* out = (float*)d_out;          // (64, 20)
    float* rec = out + 64 * 20;          // (64, 100, 10000)

    float *e, *gi, *y, *fcin, *wt;
    cudaGetSymbolAddress((void**)&e,    g_e);
    cudaGetSymbolAddress((void**)&gi,   g_gi);
    cudaGetSymbolAddress((void**)&y,    g_y);
    cudaGetSymbolAddress((void**)&fcin, g_fcin);
    cudaGetSymbolAddress((void**)&wt,   g_wt);

    cudaFuncSetAttribute(mma_tn, cudaFuncAttributeMaxDynamicSharedMemorySize, MMA_SMEM);

    dim3 gruGrid(BATCH, 2);

    // 0. pre-round the 4 Wih weight sets to tf32 (rna), one launch.
    //    recW is consumed raw (HW truncation) — saves the 10 MB cvt pass.
    cvt4<<<864, 256>>>((const float4*)eWih0, (float4*)(wt + 0),
                       (const float4*)eWih1, (float4*)(wt + 98304),
                       (const float4*)dWih0, (float4*)(wt + 294912),
                       (const float4*)dWih1, (float4*)(wt + 688128));

    // 1. embedding (float4, tf32-rounded output)
    embed_kernel<<<800, 256>>>(x, emb, e);

    // 2. encoder layer 0
    mma_tn<<<dim3(6, 50), 256, MMA_SMEM>>>(e, 128, wt + 0, ebih0, gi, 6400, 768, 128);
    gru_kernel<<<gruGrid, 384>>>(gi, TSEQ, 1, eWhh0, ebhh0, y, fcin + 0);

    // 3. encoder layer 1
    mma_tn<<<dim3(6, 50), 256, MMA_SMEM>>>(y, 256, wt + 98304, ebih1, gi, 6400, 768, 256);
    gru_kernel<<<gruGrid, 384>>>(gi, TSEQ, 1, eWhh1, ebhh1, y, fcin + 256);

    // 4. decoder layer 0 (constant input over T; raw fp32 A — HW truncation)
    mma_tn<<<dim3(6, 1), 256, MMA_SMEM>>>(fcin, 1024, wt + 294912, dbih0, gi, 64, 768, 512);
    gru_kernel<<<gruGrid, 384>>>(gi, 1, 0, dWhh0, dbhh0, y, fcin + 512);

    // 5. decoder layer 1 (output y = rec_seq)
    mma_tn<<<dim3(6, 50), 256, MMA_SMEM>>>(y, 256, wt + 688128, dbih1, gi, 6400, 768, 256);
    gru_kernel<<<gruGrid, 384>>>(gi, TSEQ, 1, dWhh1, dbhh1, y, fcin + 768);

    // 6. classifier head (fp32 GEMV, warp per output)
    fc_kernel<<<160, 256>>>(fcin, fcW, fcb, out);

    // 7. reconstruction: rec = rec_seq @ rec_W^T + rec_b  (raw recW, HW truncation)
    mma_tn<<<dim3(79, 50), 256, MMA_SMEM>>>(y, 256, recW, recb, rec, 6400, 10000, 256);
}

// round 17
// speedup vs baseline: 1.1344x; 1.1127x over previous
#include <cuda_runtime.h>
#include <math.h>

#define TSEQ 100
#define BATCH 64
#define HGRU  128
#define G3    384   // 3*H

// ---------------- tf32 helpers ----------------
__device__ __forceinline__ unsigned f2tf32(float x) {
    unsigned u;
    asm("cvt.rna.tf32.f32 %0, %1;" : "=r"(u) : "f"(x));
    return u;
}

__device__ __forceinline__ void mma_tf32v(float* d, const unsigned* a, const unsigned* b) {
    asm volatile(
        "mma.sync.aligned.m16n8k8.row.col.f32.tf32.tf32.f32 "
        "{%0,%1,%2,%3}, {%4,%5,%6,%7}, {%8,%9}, {%0,%1,%2,%3};"
        : "+f"(d[0]), "+f"(d[1]), "+f"(d[2]), "+f"(d[3])
        : "r"(a[0]), "r"(a[1]), "r"(a[2]), "r"(a[3]),
          "r"(b[0]), "r"(b[1]));
}

// cp.async helpers
#define CPA(dst, src, sz) \
    asm volatile("cp.async.ca.shared.global [%0], [%1], 16, %2;" :: "r"(dst), "l"(src), "r"(sz))
#define CPC()  asm volatile("cp.async.commit_group;")
#define CPW0() asm volatile("cp.async.wait_group 0;")
#define CPW1() asm volatile("cp.async.wait_group 1;")

#define FMA2(acc, w, h) \
    asm("fma.rn.f32x2 %0, %1, %2, %0;" : "+l"(acc) : "l"(w), "l"(h))

// ---------------- scratch (static __device__, no allocation) ----------------
__device__ float g_e[6400 * 128];      // embedded input, tf32-rounded
__device__ float g_gi[6400 * 768];     // gi for both directions (fp32)
__device__ float g_y[6400 * 256];      // layer output, tf32-rounded
__device__ float g_fcin[64 * 1024];    // [enc_h(512) | dec_h(512)], full fp32
__device__ float g_wt[884736];         // tf32 Wih: enc0@0, enc1@98304, dec0@294912, dec1@688128

// ---------------- fused prep: tf32-round 4 Wih regions + embedding gather ----------------
// blocks 0..863: weight cvt (221184 float4); blocks 864..1663: embed (204800 float4)
__global__ void prep_kernel(const float4* __restrict__ s0, float4* __restrict__ d0,
                            const float4* __restrict__ s1, float4* __restrict__ d1,
                            const float4* __restrict__ s2, float4* __restrict__ d2,
                            const float4* __restrict__ s3, float4* __restrict__ d3,
                            const int* __restrict__ x,
                            const float* __restrict__ emb,
                            float* __restrict__ e) {
    int blk = blockIdx.x;
    if (blk < 864) {
        int i = blk * 256 + threadIdx.x;
        const float4* s; float4* d; int off;
        if      (i < 24576)  { s = s0; d = d0; off = i; }
        else if (i < 73728)  { s = s1; d = d1; off = i - 24576; }
        else if (i < 172032) { s = s2; d = d2; off = i - 73728; }
        else if (i < 221184) { s = s3; d = d3; off = i - 172032; }
        else return;
        float4 v = s[off];
        v.x = __uint_as_float(f2tf32(v.x));
        v.y = __uint_as_float(f2tf32(v.y));
        v.z = __uint_as_float(f2tf32(v.z));
        v.w = __uint_as_float(f2tf32(v.w));
        d[off] = v;
    } else {
        int idx = (blk - 864) * 256 + threadIdx.x;   // 204800 float4
        if (idx >= 6400 * 32) return;
        int row = idx >> 5;
        int c4  = idx & 31;
        int v = x[row];
        if (v > 9999) v = 9999;
        if (v < 0)    v = 0;
        float4 t = ((const float4*)emb)[v * 32 + c4];
        t.x = __uint_as_float(f2tf32(t.x));
        t.y = __uint_as_float(f2tf32(t.y));
        t.z = __uint_as_float(f2tf32(t.z));
        t.w = __uint_as_float(f2tf32(t.w));
        ((float4*)e)[row * 32 + c4] = t;
    }
}

// ---------------- classifier head GEMV: warp per output ----------------
__global__ void fc_kernel(const float* __restrict__ fcin,   // (64, 1024)
                          const float* __restrict__ W,      // (20, 1024)
                          const float* __restrict__ bias,   // (20)
                          float* __restrict__ out) {        // (64, 20)
    int wid  = (blockIdx.x * blockDim.x + threadIdx.x) >> 5;
    int lane = threadIdx.x & 31;
    if (wid >= 64 * 20) return;
    int m = wid / 20, n = wid % 20;
    const float4* a = (const float4*)(fcin + m * 1024);
    const float4* w = (const float4*)(W    + n * 1024);
    float s = 0.f;
#pragma unroll
    for (int i = lane; i < 256; i += 32) {
        float4 x = a[i], y = w[i];
        s += x.x * y.x + x.y * y.y + x.z * y.z + x.w * y.w;
    }
#pragma unroll
    for (int o = 16; o; o >>= 1) s += __shfl_xor_sync(0xffffffffu, s, o);
    if (lane == 0) out[m * 20 + n] = s + bias[n];
}

// ---------------- GRU recurrence: (column, k-half) layout, 256 threads ----------------
// Thread T: column c = T&127, k-half = T>>7. Each thread computes ALL THREE gate
// rows (r,z,n of column c) over its 64-k half: 96 FMA2. No shfl tree, no sgi smem
// (tail thread prefetches its own 3 gi values), tail keeps its own partials in
// registers and reads only the other half's 3 partials from sp[][].
__global__ void __launch_bounds__(256, 1)
gru_kernel(const float* __restrict__ gi_base, int rb, int rt,
           const float* __restrict__ Whh,   // (2, 384, 128)
           const float* __restrict__ bhh,   // (2, 384)
           float* __restrict__ y,           // (B, T, 256), written tf32-rounded
           float* __restrict__ hfin) {
    __shared__ __align__(16) float sh[128];
    __shared__ float sp[3][128];

    int T    = threadIdx.x;   // 0..255
    int c    = T & 127;
    int half = T >> 7;        // 0 or 1
    int b    = blockIdx.x;
    int dir  = blockIdx.y;
    int kb   = half * 64;     // k offset (floats)

    const float* gi = gi_base + dir * G3;

    // weights: w2[g][i] = W[g*128+c][kb+2i .. +1]
    unsigned long long w2[3][32];
#pragma unroll
    for (int g = 0; g < 3; g++) {
        const unsigned long long* Wr =
            (const unsigned long long*)(Whh + (size_t)(dir * G3 + g * HGRU + c) * HGRU + kb);
#pragma unroll
        for (int i = 0; i < 32; i++) w2[g][i] = Wr[i];
    }

    float bh0 = 0.f, bh1 = 0.f, bh2 = 0.f;
    if (T < HGRU) {
        bh0 = bhh[dir * G3 + c];
        bh1 = bhh[dir * G3 + HGRU + c];
        bh2 = bhh[dir * G3 + 2 * HGRU + c];
        sh[c] = 0.f;
    }
    __syncthreads();

    const ulonglong2* sh2 = (const ulonglong2*)sh;   // 32 x 16B; our half: [half*16, half*16+16)

    // prefetch gi for t=0 (tail threads only)
    float g0 = 0.f, g1 = 0.f, g2 = 0.f;
    if (T < HGRU) {
        int tt0 = dir ? (TSEQ - 1) : 0;
        int row = (b * rb + tt0 * rt) * 768;
        g0 = gi[row + c];
        g1 = gi[row + HGRU + c];
        g2 = gi[row + 2 * HGRU + c];
    }

    for (int t = 0; t < TSEQ; t++) {
        int tt = dir ? (TSEQ - 1 - t) : t;

        // prefetch next step's gi — consumed a full step later
        float n0 = 0.f, n1 = 0.f, n2 = 0.f;
        if (T < HGRU && t + 1 < TSEQ) {
            int ttn = dir ? (TSEQ - 2 - t) : (t + 1);
            int row = (b * rb + ttn * rt) * 768;
            n0 = gi[row + c];
            n1 = gi[row + HGRU + c];
            n2 = gi[row + 2 * HGRU + c];
        }

        unsigned long long a00 = 0ULL, a01 = 0ULL;   // gate r
        unsigned long long a10 = 0ULL, a11 = 0ULL;   // gate z
        unsigned long long a20 = 0ULL, a21 = 0ULL;   // gate n
#pragma unroll
        for (int ch = 0; ch < 4; ch++) {
            const ulonglong2* p = sh2 + half * 16 + ch * 4;
            ulonglong2 h0 = p[0], h1 = p[1], h2 = p[2], h3 = p[3];   // 16 floats
            FMA2(a00, w2[0][ch * 8 + 0], h0.x); FMA2(a01, w2[0][ch * 8 + 1], h0.y);
            FMA2(a00, w2[0][ch * 8 + 2], h1.x); FMA2(a01, w2[0][ch * 8 + 3], h1.y);
            FMA2(a00, w2[0][ch * 8 + 4], h2.x); FMA2(a01, w2[0][ch * 8 + 5], h2.y);
            FMA2(a00, w2[0][ch * 8 + 6], h3.x); FMA2(a01, w2[0][ch * 8 + 7], h3.y);
            FMA2(a10, w2[1][ch * 8 + 0], h0.x); FMA2(a11, w2[1][ch * 8 + 1], h0.y);
            FMA2(a10, w2[1][ch * 8 + 2], h1.x); FMA2(a11, w2[1][ch * 8 + 3], h1.y);
            FMA2(a10, w2[1][ch * 8 + 4], h2.x); FMA2(a11, w2[1][ch * 8 + 5], h2.y);
            FMA2(a10, w2[1][ch * 8 + 6], h3.x); FMA2(a11, w2[1][ch * 8 + 7], h3.y);
            FMA2(a20, w2[2][ch * 8 + 0], h0.x); FMA2(a21, w2[2][ch * 8 + 1], h0.y);
            FMA2(a20, w2[2][ch * 8 + 2], h1.x); FMA2(a21, w2[2][ch * 8 + 3], h1.y);
            FMA2(a20, w2[2][ch * 8 + 4], h2.x); FMA2(a21, w2[2][ch * 8 + 5], h2.y);
            FMA2(a20, w2[2][ch * 8 + 6], h3.x); FMA2(a21, w2[2][ch * 8 + 7], h3.y);
        }

        float t0, t1, t2;
        {
            float lo, hi;
            asm("add.rn.f32x2 %0, %0, %1;" : "+l"(a00) : "l"(a01));
            asm("add.rn.f32x2 %0, %0, %1;" : "+l"(a10) : "l"(a11));
            asm("add.rn.f32x2 %0, %0, %1;" : "+l"(a20) : "l"(a21));
            asm("mov.b64 {%0,%1}, %2;" : "=f"(lo), "=f"(hi) : "l"(a00)); t0 = lo + hi;
            asm("mov.b64 {%0,%1}, %2;" : "=f"(lo), "=f"(hi) : "l"(a10)); t1 = lo + hi;
            asm("mov.b64 {%0,%1}, %2;" : "=f"(lo), "=f"(hi) : "l"(a20)); t2 = lo + hi;
        }

        if (T >= HGRU) {
            sp[0][c] = t0;
            sp[1][c] = t1;
            sp[2][c] = t2;
        }
        __syncthreads();

        if (T < HGRU) {
            float ghr = t0 + sp[0][c] + bh0;
            float ghz = t1 + sp[1][c] + bh1;
            float ghn = t2 + sp[2][c] + bh2;
            float r = __fdividef(1.f, 1.f + __expf(-(g0 + ghr)));
            float z = __fdividef(1.f, 1.f + __expf(-(g1 + ghz)));
            float nx = g2 + r * ghn;
            float et = __expf(-2.f * nx);
            float n  = __fdividef(1.f - et, 1.f + et);   // tanh(nx)
            float hn = n + z * (sh[c] - n);
            sh[c] = hn;
            y[(b * TSEQ + tt) * 256 + dir * HGRU + c] = __uint_as_float(f2tf32(hn));
        }
        __syncthreads();

        g0 = n0; g1 = n1; g2 = n2;
    }
    if (T < HGRU) hfin[b * 1024 + dir * HGRU + c] = sh[c];
}

// ---------------- tf32 MMA GEMM, cp.async 3-stage + ldmatrix fragment loads ----------------
// Inputs may be raw fp32: HMMA-tf32 truncates the low mantissa bits (RZ).
#define MMA_STAGES 3
#define MMA_BUF    (128 * 36)                       // floats per operand per stage
#define MMA_SMEM   (MMA_STAGES * MMA_BUF * 4 * 2)   // 110592 B
__global__ void __launch_bounds__(256, 2)
mma_tn(const float* __restrict__ A, int lda,
       const float* __restrict__ W,     // (N, K)
       const float* __restrict__ bias,  // (N)
       float* __restrict__ C,
       int M, int N, int K) {
    extern __shared__ float smem[];
    float* As = smem;                        // [3][128][36]
    float* Bs = smem + MMA_STAGES * MMA_BUF;

    int t    = threadIdx.x;
    int lane = t & 31;
    int warp = t >> 5;
    int m0 = blockIdx.y * 128;
    int n0 = blockIdx.x * 128;
    int wm = (warp & 3) * 32;
    int wn = (warp >> 2) * 64;
    int r  = lane >> 2;       // 0..7
    int c  = lane & 3;        // 0..3

    unsigned sbaseA = (unsigned)__cvta_generic_to_shared(As);
    unsigned sbaseB = (unsigned)__cvta_generic_to_shared(Bs);

    // lane-constant ldmatrix address parts
    int grp = lane >> 3, q = lane & 7;
    unsigned LA = (((unsigned)((grp & 1) * 8 + q)) * 36 + (unsigned)((grp >> 1) * 4)) * 4;
    unsigned LB = (((unsigned)((grp >> 1) * 8 + q)) * 36 + (unsigned)((grp & 1) * 4)) * 4;

    float acc[2][8][4];
#pragma unroll
    for (int mf = 0; mf < 2; mf++)
#pragma unroll
        for (int nf = 0; nf < 8; nf++)
#pragma unroll
            for (int i = 0; i < 4; i++) acc[mf][nf][i] = 0.f;

    int nch = K >> 5;    // K/32 chunks

    auto stage = [&](int buf, int k0) {
#pragma unroll
        for (int i = 0; i < 4; i++) {
            int idx = i * 256 + t;
            int row = idx >> 3;
            int c4  = (idx & 7) * 4;
            unsigned off = ((unsigned)(buf * 128 + row) * 36 + c4) * 4;
            CPA(sbaseA + off, &A[(size_t)(m0 + row) * lda + k0 + c4], (m0 + row < M) ? 16 : 0);
            CPA(sbaseB + off, &W[(size_t)(n0 + row) * K   + k0 + c4], (n0 + row < N) ? 16 : 0);
        }
    };

    auto compute = [&](int buf) {
        unsigned aB = sbaseA + (unsigned)buf * (MMA_BUF * 4);
        unsigned bB = sbaseB + (unsigned)buf * (MMA_BUF * 4);
#pragma unroll
        for (int ks = 0; ks < 4; ks++) {
            int kb = ks * 8;
            unsigned a[2][4];
#pragma unroll
            for (int mf = 0; mf < 2; mf++) {
                unsigned addr = aB + ((unsigned)((wm + mf * 16) * 36 + kb)) * 4 + LA;
                asm volatile(
                    "ldmatrix.sync.aligned.m8n8.x4.shared.b16 {%0,%1,%2,%3}, [%4];"
                    : "=r"(a[mf][0]), "=r"(a[mf][1]), "=r"(a[mf][2]), "=r"(a[mf][3])
                    : "r"(addr));
            }
#pragma unroll
            for (int p = 0; p < 4; p++) {
                unsigned b[4];
                unsigned addr = bB + ((unsigned)((wn + 16 * p) * 36 + kb)) * 4 + LB;
                asm volatile(
                    "ldmatrix.sync.aligned.m8n8.x4.shared.b16 {%0,%1,%2,%3}, [%4];"
                    : "=r"(b[0]), "=r"(b[1]), "=r"(b[2]), "=r"(b[3])
                    : "r"(addr));
                mma_tf32v(acc[0][2 * p],     a[0], b);
                mma_tf32v(acc[1][2 * p],     a[1], b);
                mma_tf32v(acc[0][2 * p + 1], a[0], b + 2);
                mma_tf32v(acc[1][2 * p + 1], a[1], b + 2);
            }
        }
    };

    // prologue: 2 chunks in flight
    stage(0, 0);  CPC();
    if (nch > 1) { stage(1, 32); CPC(); }

    int buf = 0;            // buf == ci % 3, maintained by rotation
    for (int ci = 0; ci < nch; ci++) {
        if (ci < nch - 1) { CPW1(); } else { CPW0(); }
        __syncthreads();
        if (ci + 2 < nch) {
            int nb = buf + 2; if (nb >= 3) nb -= 3;
            stage(nb, (ci + 2) * 32); CPC();
        }
        compute(buf);
        if (++buf == 3) buf = 0;
    }

    // epilogue
#pragma unroll
    for (int mf = 0; mf < 2; mf++) {
#pragma unroll
        for (int nf = 0; nf < 8; nf++) {
            int n = n0 + wn + nf * 8 + 2 * c;
            if (n >= N) continue;
            float bv0 = bias[n];
            float bv1 = bias[n + 1];
            int m = m0 + wm + mf * 16 + r;
            if (m < M) {
                *(float2*)&C[(size_t)m * N + n] =
                    make_float2(acc[mf][nf][0] + bv0, acc[mf][nf][1] + bv1);
            }
            if (m + 8 < M) {
                *(float2*)&C[(size_t)(m + 8) * N + n] =
                    make_float2(acc[mf][nf][2] + bv0, acc[mf][nf][3] + bv1);
            }
        }
    }
}

// ---------------- driver ----------------
extern "C" void kernel_launch(void* const* d_in, const int* in_sizes, int n_in,
                              void* d_out, int out_size) {
    const int* x         = (const int*)d_in[0];
    const float* emb     = (const float*)d_in[1];
    const float* eWih0   = (const float*)d_in[2];
    const float* eWhh0   = (const float*)d_in[3];
    const float* ebih0   = (const float*)d_in[4];
    const float* ebhh0   = (const float*)d_in[5];
    const float* eWih1   = (const float*)d_in[6];
    const float* eWhh1   = (const float*)d_in[7];
    const float* ebih1   = (const float*)d_in[8];
    const float* ebhh1   = (const float*)d_in[9];
    const float* dWih0   = (const float*)d_in[10];
    const float* dWhh0   = (const float*)d_in[11];
    const float* dbih0   = (const float*)d_in[12];
    const float* dbhh0   = (const float*)d_in[13];
    const float* dWih1   = (const float*)d_in[14];
    const float* dWhh1   = (const float*)d_in[15];
    const float* dbih1   = (const float*)d_in[16];
    const float* dbhh1   = (const float*)d_in[17];
    const float* fcW     = (const float*)d_in[18];
    const float* fcb     = (const float*)d_in[19];
    const float* recW    = (const float*)d_in[20];
    const float* recb    = (const float*)d_in[21];

    float* out = (float*)d_out;          // (64, 20)
    float* rec = out + 64 * 20;          // (64, 100, 10000)

    float *e, *gi, *y, *fcin, *wt;
    cudaGetSymbolAddress((void**)&e,    g_e);
    cudaGetSymbolAddress((void**)&gi,   g_gi);
    cudaGetSymbolAddress((void**)&y,    g_y);
    cudaGetSymbolAddress((void**)&fcin, g_fcin);
    cudaGetSymbolAddress((void**)&wt,   g_wt);

    cudaFuncSetAttribute(mma_tn, cudaFuncAttributeMaxDynamicSharedMemorySize, MMA_SMEM);

    dim3 gruGrid(BATCH, 2);

    // 0. fused prep: tf32-round the 4 Wih sets + embedding gather (one launch)
    prep_kernel<<<1664, 256>>>((const float4*)eWih0, (float4*)(wt + 0),
                               (const float4*)eWih1, (float4*)(wt + 98304),
                               (const float4*)dWih0, (float4*)(wt + 294912),
                               (const float4*)dWih1, (float4*)(wt + 688128),
                               x, emb, e);

    // 2. encoder layer 0
    mma_tn<<<dim3(6, 50), 256, MMA_SMEM>>>(e, 128, wt + 0, ebih0, gi, 6400, 768, 128);
    gru_kernel<<<gruGrid, 256>>>(gi, TSEQ, 1, eWhh0, ebhh0, y, fcin + 0);

    // 3. encoder layer 1
    mma_tn<<<dim3(6, 50), 256, MMA_SMEM>>>(y, 256, wt + 98304, ebih1, gi, 6400, 768, 256);
    gru_kernel<<<gruGrid, 256>>>(gi, TSEQ, 1, eWhh1, ebhh1, y, fcin + 256);

    // 4. decoder layer 0 (constant input over T; raw fp32 A — HW truncation)
    mma_tn<<<dim3(6, 1), 256, MMA_SMEM>>>(fcin, 1024, wt + 294912, dbih0, gi, 64, 768, 512);
    gru_kernel<<<gruGrid, 256>>>(gi, 1, 0, dWhh0, dbhh0, y, fcin + 512);

    // 5. decoder layer 1 (output y = rec_seq)
    mma_tn<<<dim3(6, 50), 256, MMA_SMEM>>>(y, 256, wt + 688128, dbih1, gi, 6400, 768, 256);
    gru_kernel<<<gruGrid, 256>>>(gi, TSEQ, 1, dWhh1, dbhh1, y, fcin + 768);

    // 6. classifier head (fp32 GEMV, warp per output)
    fc_kernel<<<160, 256>>>(fcin, fcW, fcb, out);

    // 7. reconstruction: rec = rec_seq @ rec_W^T + rec_b  (raw recW, HW truncation)
    mma_tn<<<dim3(79, 50), 256, MMA_SMEM>>>(y, 256, recW, recb, rec, 6400, 10000, 256);
}